// round 6
// baseline (speedup 1.0000x reference)
#include <cuda_runtime.h>
#include <cuda_fp16.h>
#include <cuda_bf16.h>
#include <cstdint>

#define NN   50000
#define EE   1600000
#define HH   8
#define FF   16
#define INF  256
#define HF   128
#define SLOPE 0.2f

#define MTILE 128
#define KC    64
#define LDT   72                               // padded bf16 row stride
#define GEMM_GRID ((NN + MTILE - 1) / MTILE)   // 391

// dynamic smem layout (bytes)
#define SM_AHI  0
#define SM_ALO  18432
#define SM_BHI  36864
#define SM_BLO  55296
#define SM_AL   73728
#define SM_AR   74240
#define SMEM_TOTAL 74752

// ---------------- scratch ----------------------------------------------------
__device__ __align__(16) __half g_feath[NN * HF];   // 12.8 MB
__device__ float g_el[NN * HH];
__device__ float g_er[NN * HH];
__device__ float g_mbias[FF];
__device__ int   g_cnt[NN];
__device__ int   g_off[NN + 1];
__device__ int   g_cursor[NN];
__device__ int   g_csr_src[EE];
__device__ int   g_is64;
__device__ __align__(16) __nv_bfloat16 g_Bhi[HF * INF];  // [n][k] row-major
__device__ __align__(16) __nv_bfloat16 g_Blo[HF * INF];

// ---------------- mma.sync wrapper -------------------------------------------
__device__ __forceinline__ void mma16816(float* d, unsigned a0, unsigned a1,
                                         unsigned a2, unsigned a3,
                                         unsigned b0, unsigned b1) {
    asm volatile(
        "mma.sync.aligned.m16n8k16.row.col.f32.bf16.bf16.f32 "
        "{%0,%1,%2,%3}, {%4,%5,%6,%7}, {%8,%9}, {%0,%1,%2,%3};"
        : "+f"(d[0]), "+f"(d[1]), "+f"(d[2]), "+f"(d[3])
        : "r"(a0), "r"(a1), "r"(a2), "r"(a3), "r"(b0), "r"(b1));
}

// ---------------- detect index dtype -----------------------------------------
__global__ void detect_kernel(const void* __restrict__ dstp) {
    if (threadIdx.x == 0 && blockIdx.x == 0) {
        const uint2* p = (const uint2*)dstp;
        unsigned any = 0;
        for (int i = 0; i < 256; i++) any |= p[i].y;
        g_is64 = (any == 0u) ? 1 : 0;
    }
}

// ---------------- zero counters + mean-bias ----------------------------------
__global__ void zero_cnt_kernel(const float* __restrict__ bias) {
    int i = blockIdx.x * blockDim.x + threadIdx.x;
    if (i < NN) g_cnt[i] = 0;
    if (i < FF) {
        float s = 0.f;
#pragma unroll
        for (int h = 0; h < HH; h++) s += bias[h * FF + i];
        g_mbias[i] = 0.125f * s;
    }
}

// ---------------- prep: W -> transposed bf16 hi/lo images ([n][k]) -----------
__global__ void prepB_kernel(const float* __restrict__ W) {
    int i = blockIdx.x * blockDim.x + threadIdx.x;   // 0..32767
    if (i >= HF * INF) return;
    int n = i >> 8;
    int k = i & 255;
    float w = W[(size_t)k * HF + n];
    __nv_bfloat16 hi = __float2bfloat16(w);
    __nv_bfloat16 lo = __float2bfloat16(w - __bfloat162float(hi));
    g_Bhi[i] = hi;
    g_Blo[i] = lo;
}

// ---------------- dst histogram (reads raw indices) ---------------------------
__global__ void hist_kernel(const void* __restrict__ dstp) {
    int stride = gridDim.x * blockDim.x;
    int is64 = g_is64;
    for (int i = blockIdx.x * blockDim.x + threadIdx.x; i < EE; i += stride) {
        int d = is64 ? (int)((const long long*)dstp)[i] : ((const int*)dstp)[i];
        d = min(max(d, 0), NN - 1);
        atomicAdd(&g_cnt[d], 1);
    }
}

// ---------------- mma.sync bf16x3 GEMM + fused el/er + fp16 feat --------------
__global__ __launch_bounds__(256, 2)
void gemm_kernel(const float* __restrict__ x,
                 const float* __restrict__ al,
                 const float* __restrict__ ar) {
    extern __shared__ char smem[];
    __nv_bfloat16* sAhi = (__nv_bfloat16*)(smem + SM_AHI);  // [128][72]
    __nv_bfloat16* sAlo = (__nv_bfloat16*)(smem + SM_ALO);
    __nv_bfloat16* sBhi = (__nv_bfloat16*)(smem + SM_BHI);  // [n=128][72]
    __nv_bfloat16* sBlo = (__nv_bfloat16*)(smem + SM_BLO);
    float* sal = (float*)(smem + SM_AL);
    float* sar = (float*)(smem + SM_AR);

    int tid  = threadIdx.x;
    int wid  = tid >> 5;
    int lane = tid & 31;
    int row0 = blockIdx.x * MTILE;
    int wm   = wid >> 2;     // 0..1  (64 rows)
    int wn   = wid & 3;      // 0..3  (32 cols)

    if (tid < HF) { sal[tid] = al[tid]; sar[tid] = ar[tid]; }

    float acc[4][4][4];
#pragma unroll
    for (int mt = 0; mt < 4; mt++)
#pragma unroll
        for (int nt = 0; nt < 4; nt++)
#pragma unroll
            for (int q = 0; q < 4; q++) acc[mt][nt][q] = 0.f;

    for (int c = 0; c < 4; c++) {
        int k0 = c * KC;
        __syncthreads();
        // stage A chunk (fp32 -> bf16 hi/lo), 2048 float4
        for (int t = tid; t < 2048; t += 256) {
            int r  = t >> 4;
            int kq = (t & 15) * 4;
            float4 v = make_float4(0.f, 0.f, 0.f, 0.f);
            int gr = row0 + r;
            if (gr < NN) v = *(const float4*)(x + (size_t)gr * INF + k0 + kq);
            float vv[4] = {v.x, v.y, v.z, v.w};
            __nv_bfloat16 h[4], l[4];
#pragma unroll
            for (int q = 0; q < 4; q++) {
                h[q] = __float2bfloat16(vv[q]);
                l[q] = __float2bfloat16(vv[q] - __bfloat162float(h[q]));
            }
            __nv_bfloat162 hp0 = __halves2bfloat162(h[0], h[1]);
            __nv_bfloat162 hp1 = __halves2bfloat162(h[2], h[3]);
            __nv_bfloat162 lp0 = __halves2bfloat162(l[0], l[1]);
            __nv_bfloat162 lp1 = __halves2bfloat162(l[2], l[3]);
            int off = r * LDT + kq;
            *(uint2*)&sAhi[off] = make_uint2(*(unsigned*)&hp0, *(unsigned*)&hp1);
            *(uint2*)&sAlo[off] = make_uint2(*(unsigned*)&lp0, *(unsigned*)&lp1);
        }
        // stage B chunk (copy pre-built images), 1024 uint4 each
        for (int t = tid; t < 1024; t += 256) {
            int n  = t >> 3;
            int kq = (t & 7) * 8;
            int off = n * LDT + kq;
            *(uint4*)&sBhi[off] = *(const uint4*)&g_Bhi[n * INF + k0 + kq];
            *(uint4*)&sBlo[off] = *(const uint4*)&g_Blo[n * INF + k0 + kq];
        }
        __syncthreads();

#pragma unroll
        for (int ks = 0; ks < 4; ks++) {
            int koff = ks * 16 + (lane & 3) * 2;
            unsigned bh[4][2], bl[4][2];
#pragma unroll
            for (int nt = 0; nt < 4; nt++) {
                int n = (wn * 32 + nt * 8 + (lane >> 2)) * LDT + koff;
                bh[nt][0] = *(const unsigned*)&sBhi[n];
                bh[nt][1] = *(const unsigned*)&sBhi[n + 8];
                bl[nt][0] = *(const unsigned*)&sBlo[n];
                bl[nt][1] = *(const unsigned*)&sBlo[n + 8];
            }
#pragma unroll
            for (int mt = 0; mt < 4; mt++) {
                int r = (wm * 64 + mt * 16 + (lane >> 2)) * LDT + koff;
                unsigned ah0 = *(const unsigned*)&sAhi[r];
                unsigned ah1 = *(const unsigned*)&sAhi[r + 8 * LDT];
                unsigned ah2 = *(const unsigned*)&sAhi[r + 8];
                unsigned ah3 = *(const unsigned*)&sAhi[r + 8 * LDT + 8];
                unsigned al0 = *(const unsigned*)&sAlo[r];
                unsigned al1 = *(const unsigned*)&sAlo[r + 8 * LDT];
                unsigned al2 = *(const unsigned*)&sAlo[r + 8];
                unsigned al3 = *(const unsigned*)&sAlo[r + 8 * LDT + 8];
#pragma unroll
                for (int nt = 0; nt < 4; nt++) {
                    mma16816(acc[mt][nt], ah0, ah1, ah2, ah3, bh[nt][0], bh[nt][1]);
                    mma16816(acc[mt][nt], ah0, ah1, ah2, ah3, bl[nt][0], bl[nt][1]);
                    mma16816(acc[mt][nt], al0, al1, al2, al3, bh[nt][0], bh[nt][1]);
                }
            }
        }
    }

    // epilogue: fp16 feat store + el/er from registers
#pragma unroll
    for (int mt = 0; mt < 4; mt++) {
        int rr0 = row0 + wm * 64 + mt * 16 + (lane >> 2);
        int rr1 = rr0 + 8;
        float el0[2] = {0.f, 0.f}, er0[2] = {0.f, 0.f};
        float el1[2] = {0.f, 0.f}, er1[2] = {0.f, 0.f};
#pragma unroll
        for (int nt = 0; nt < 4; nt++) {
            int col  = wn * 32 + nt * 8 + (lane & 3) * 2;
            int hsel = nt >> 1;
            float d0 = acc[mt][nt][0], d1 = acc[mt][nt][1];
            float d2 = acc[mt][nt][2], d3 = acc[mt][nt][3];
            el0[hsel] += d0 * sal[col] + d1 * sal[col + 1];
            er0[hsel] += d0 * sar[col] + d1 * sar[col + 1];
            el1[hsel] += d2 * sal[col] + d3 * sal[col + 1];
            er1[hsel] += d2 * sar[col] + d3 * sar[col + 1];
            if (rr0 < NN) {
                __half2 p = __floats2half2_rn(d0, d1);
                *(unsigned*)&g_feath[(size_t)rr0 * HF + col] = *(unsigned*)&p;
            }
            if (rr1 < NN) {
                __half2 p = __floats2half2_rn(d2, d3);
                *(unsigned*)&g_feath[(size_t)rr1 * HF + col] = *(unsigned*)&p;
            }
        }
#pragma unroll
        for (int s = 1; s <= 2; s <<= 1) {
            el0[0] += __shfl_xor_sync(0xffffffffu, el0[0], s);
            el0[1] += __shfl_xor_sync(0xffffffffu, el0[1], s);
            er0[0] += __shfl_xor_sync(0xffffffffu, er0[0], s);
            er0[1] += __shfl_xor_sync(0xffffffffu, er0[1], s);
            el1[0] += __shfl_xor_sync(0xffffffffu, el1[0], s);
            el1[1] += __shfl_xor_sync(0xffffffffu, el1[1], s);
            er1[0] += __shfl_xor_sync(0xffffffffu, er1[0], s);
            er1[1] += __shfl_xor_sync(0xffffffffu, er1[1], s);
        }
        if ((lane & 3) == 0) {
            if (rr0 < NN) {
                g_el[rr0 * HH + 2 * wn]     = el0[0];
                g_el[rr0 * HH + 2 * wn + 1] = el0[1];
                g_er[rr0 * HH + 2 * wn]     = er0[0];
                g_er[rr0 * HH + 2 * wn + 1] = er0[1];
            }
            if (rr1 < NN) {
                g_el[rr1 * HH + 2 * wn]     = el1[0];
                g_el[rr1 * HH + 2 * wn + 1] = el1[1];
                g_er[rr1 * HH + 2 * wn]     = er1[0];
                g_er[rr1 * HH + 2 * wn + 1] = er1[1];
            }
        }
    }
}

// ---------------- exclusive scan (single block, warp-shfl) --------------------
__global__ __launch_bounds__(1024) void scan_kernel() {
    __shared__ int wsum[32];
    __shared__ int carry_s;
    int lane = threadIdx.x & 31;
    int warp = threadIdx.x >> 5;
    if (threadIdx.x == 0) carry_s = 0;
    __syncthreads();
    for (int base = 0; base < NN; base += 1024) {
        int i = base + threadIdx.x;
        int v = (i < NN) ? g_cnt[i] : 0;
        int incl = v;
#pragma unroll
        for (int s = 1; s < 32; s <<= 1) {
            int t = __shfl_up_sync(0xffffffffu, incl, s);
            if (lane >= s) incl += t;
        }
        if (lane == 31) wsum[warp] = incl;
        __syncthreads();
        if (warp == 0) {
            int wv = wsum[lane];
            int wi = wv;
#pragma unroll
            for (int s = 1; s < 32; s <<= 1) {
                int t = __shfl_up_sync(0xffffffffu, wi, s);
                if (lane >= s) wi += t;
            }
            wsum[lane] = wi - wv;
        }
        __syncthreads();
        int excl = incl - v + wsum[warp] + carry_s;
        if (i < NN) { g_off[i] = excl; g_cursor[i] = excl; }
        __syncthreads();
        if (threadIdx.x == 1023) carry_s = excl + v;
        __syncthreads();
    }
    if (threadIdx.x == 0) g_off[NN] = carry_s;
}

// ---------------- scatter edges into CSR (reads raw indices) ------------------
__global__ void scatter_kernel(const void* __restrict__ srcp,
                               const void* __restrict__ dstp) {
    int stride = gridDim.x * blockDim.x;
    int is64 = g_is64;
    for (int i = blockIdx.x * blockDim.x + threadIdx.x; i < EE; i += stride) {
        int s, d;
        if (is64) {
            s = (int)((const long long*)srcp)[i];
            d = (int)((const long long*)dstp)[i];
        } else {
            s = ((const int*)srcp)[i];
            d = ((const int*)dstp)[i];
        }
        s = min(max(s, 0), NN - 1);
        d = min(max(d, 0), NN - 1);
        int p = atomicAdd(&g_cursor[d], 1);
        g_csr_src[p] = s;
    }
}

// ---------------- fused softmax-aggregate + classifier ------------------------
__global__ __launch_bounds__(256) void agg_kernel(float* __restrict__ out) {
    int gtid = blockIdx.x * blockDim.x + threadIdx.x;
    int n    = gtid >> 5;
    int lane = gtid & 31;
    if (n >= NN) return;
    int half = lane >> 4;
    int sub  = lane & 15;
    unsigned gmask = half ? 0xFFFF0000u : 0x0000FFFFu;

    float ern = (sub < HH) ? g_er[n * HH + sub] : 0.f;
    int beg = g_off[n], end = g_off[n + 1];

    float acc[8];
#pragma unroll
    for (int k = 0; k < 8; k++) acc[k] = 0.f;
    float ssum = 0.f;

    for (int i = beg + half; i < end; i += 2) {
        int sv = g_csr_src[i];
        float exv = 0.f;
        if (sub < HH) {
            float e = g_el[sv * HH + sub] + ern;
            e = fmaxf(e, 0.f) + SLOPE * fminf(e, 0.f);
            exv = __expf(e);
            ssum += exv;
        }
        float exh = __shfl_sync(gmask, exv, (half << 4) + (sub >> 1));
        uint4 f = *reinterpret_cast<const uint4*>(g_feath + (size_t)sv * HF + sub * 8);
        float2 v0 = __half22float2(*reinterpret_cast<__half2*>(&f.x));
        float2 v1 = __half22float2(*reinterpret_cast<__half2*>(&f.y));
        float2 v2 = __half22float2(*reinterpret_cast<__half2*>(&f.z));
        float2 v3 = __half22float2(*reinterpret_cast<__half2*>(&f.w));
        acc[0] += exh * v0.x; acc[1] += exh * v0.y;
        acc[2] += exh * v1.x; acc[3] += exh * v1.y;
        acc[4] += exh * v2.x; acc[5] += exh * v2.y;
        acc[6] += exh * v3.x; acc[7] += exh * v3.y;
    }
    __syncwarp();

#pragma unroll
    for (int k = 0; k < 8; k++) acc[k] += __shfl_xor_sync(0xffffffffu, acc[k], 16);
    ssum += __shfl_xor_sync(0xffffffffu, ssum, 16);

    float inv = 0.f;
    if (sub < HH) inv = 1.f / fmaxf(ssum, 1e-9f);
    float invh = __shfl_sync(0xffffffffu, inv, (half << 4) + (sub >> 1));
#pragma unroll
    for (int k = 0; k < 8; k++) acc[k] *= invh;

#pragma unroll
    for (int d = 2; d < 16; d <<= 1)
#pragma unroll
        for (int k = 0; k < 8; k++) acc[k] += __shfl_xor_sync(0xffffffffu, acc[k], d);

    if (lane < 2) {
        float4 o0, o1;
        o0.x = acc[0] * 0.125f + g_mbias[lane * 8 + 0];
        o0.y = acc[1] * 0.125f + g_mbias[lane * 8 + 1];
        o0.z = acc[2] * 0.125f + g_mbias[lane * 8 + 2];
        o0.w = acc[3] * 0.125f + g_mbias[lane * 8 + 3];
        o1.x = acc[4] * 0.125f + g_mbias[lane * 8 + 4];
        o1.y = acc[5] * 0.125f + g_mbias[lane * 8 + 5];
        o1.z = acc[6] * 0.125f + g_mbias[lane * 8 + 6];
        o1.w = acc[7] * 0.125f + g_mbias[lane * 8 + 7];
        ((float4*)out)[n * 4 + lane * 2 + 0] = o0;
        ((float4*)out)[n * 4 + lane * 2 + 1] = o1;
    }
}

// ---------------- launch ------------------------------------------------------
extern "C" void kernel_launch(void* const* d_in, const int* in_sizes, int n_in,
                              void* d_out, int out_size) {
    const float* x    = (const float*)d_in[0];
    const float* W    = (const float*)d_in[1];
    const float* al   = (const float*)d_in[2];
    const float* ar   = (const float*)d_in[3];
    const float* bias = (const float*)d_in[4];
    const void*  src  = d_in[5];
    const void*  dst  = d_in[6];
    float* out = (float*)d_out;

    cudaFuncSetAttribute(gemm_kernel, cudaFuncAttributeMaxDynamicSharedMemorySize, SMEM_TOTAL);

    detect_kernel<<<1, 32>>>(dst);
    zero_cnt_kernel<<<(NN + 255) / 256, 256>>>(bias);
    prepB_kernel<<<128, 256>>>(W);
    hist_kernel<<<2048, 256>>>(dst);
    gemm_kernel<<<GEMM_GRID, 256, SMEM_TOTAL>>>(x, al, ar);
    scan_kernel<<<1, 1024>>>();
    scatter_kernel<<<2048, 256>>>(src, dst);
    agg_kernel<<<(NN * 32 + 255) / 256, 256>>>(out);
}